// round 2
// baseline (speedup 1.0000x reference)
#include <cuda_runtime.h>
#include <cuda_bf16.h>

// GAT forward, fused pipeline:
//   K1 gemm_dual:  proj = x@W (scratch) AND acc = x@skip_w (d_out),
//                  sharing one A (x) smem tile per block.
//   K2 node_scores: s_src/s_trg per (node, head); also zeroes denom
//   K3 edge_scores: ex = exp(leaky(s_src[src]+s_trg[trg])), denom[trg] += ex
//   K4 edge_agg:    d_out[trg] += proj[src] * (ex / denom[trg])      (red.v4)
//   K5 finalize:    d_out = leaky(d_out + bias)
// Global max subtraction from the reference cancels in the softmax ratio
// (epsilon contribution ~1e-12 relative) and is omitted.

#define N_NODES 50000
#define E_EDGES 800000
#define KDIM    256
#define HF      256
#define NHEADS  4

#define NEG_SLOPE 0.2f

// ---- scratch (device globals; no allocations allowed) ----
__device__ __align__(16) float g_proj[N_NODES * HF];
__device__ __align__(16) float g_ssrc[N_NODES * NHEADS];
__device__ __align__(16) float g_strg[N_NODES * NHEADS];
__device__ __align__(16) float g_ex[E_EDGES * NHEADS];
__device__ __align__(16) float g_denom[N_NODES * NHEADS];

__device__ __forceinline__ float lrelu(float v) {
    return v > 0.f ? v : NEG_SLOPE * v;
}

__device__ __forceinline__ void red_add_v4(float* addr, float4 v) {
    asm volatile("red.global.add.v4.f32 [%0], {%1, %2, %3, %4};"
                 :: "l"(addr), "f"(v.x), "f"(v.y), "f"(v.z), "f"(v.w)
                 : "memory");
}

// ============================================================================
// K1: dual GEMM with shared A tile.  grid = (4, ceil(N/64)), block = 256.
// Each block: rows [by*64, by*64+64), cols [bx*64, bx*64+64) of BOTH
//   proj = x@W  and  acc = x@skip_w.
// Tile 64x64, BK=32, per-thread 4x4 micro-tile for each of the two outputs.
// As stored transposed [k][m] (pad to 65 to kill bank conflicts).
// ============================================================================
__global__ __launch_bounds__(256) void gemm_dual(
    const float* __restrict__ x, const float* __restrict__ W,
    const float* __restrict__ skipw, float* __restrict__ proj,
    float* __restrict__ acc)
{
    __shared__ __align__(16) float As[32][65];   // [k][m], padded
    __shared__ __align__(16) float BsW[32][64];  // [k][n]  (W)
    __shared__ __align__(16) float BsS[32][64];  // [k][n]  (skip_w)

    const int colbase = blockIdx.x * 64;
    const int row0 = blockIdx.y * 64;
    const int tid = threadIdx.x;
    const int tx = tid & 15;          // col group
    const int ty = tid >> 4;          // row group
    const int tx4 = tx * 4;
    const int ty4 = ty * 4;

    float accW[4][4] = {};
    float accS[4][4] = {};

    for (int kt = 0; kt < KDIM; kt += 32) {
        // A tile: 64 rows x 32 k, transposed into As[k][m]
        #pragma unroll
        for (int i = 0; i < 2; i++) {
            int v = tid + i * 256;        // float4 index within tile
            int r = v >> 3;               // row 0..63
            int c = (v & 7) * 4;          // k-col 0,4,...,28
            int gr = row0 + r;
            float4 av = (gr < N_NODES)
                ? *(const float4*)(x + (long)gr * KDIM + kt + c)
                : make_float4(0.f, 0.f, 0.f, 0.f);
            As[c + 0][r] = av.x;
            As[c + 1][r] = av.y;
            As[c + 2][r] = av.z;
            As[c + 3][r] = av.w;
        }
        // B tiles: 32 k x 64 cols each (W and skip_w)
        #pragma unroll
        for (int i = 0; i < 2; i++) {
            int v = tid + i * 256;
            int r = v >> 4;               // k 0..31
            int c = (v & 15) * 4;         // col 0..60
            long off = (long)(kt + r) * HF + colbase + c;
            *(float4*)&BsW[r][c] = *(const float4*)(W + off);
            *(float4*)&BsS[r][c] = *(const float4*)(skipw + off);
        }
        __syncthreads();

        #pragma unroll
        for (int k = 0; k < 32; ++k) {
            float a0 = As[k][ty4 + 0];
            float a1 = As[k][ty4 + 1];
            float a2 = As[k][ty4 + 2];
            float a3 = As[k][ty4 + 3];
            float4 bw = *(const float4*)&BsW[k][tx4];
            float4 bs = *(const float4*)&BsS[k][tx4];
            accW[0][0] += a0 * bw.x; accW[0][1] += a0 * bw.y;
            accW[0][2] += a0 * bw.z; accW[0][3] += a0 * bw.w;
            accW[1][0] += a1 * bw.x; accW[1][1] += a1 * bw.y;
            accW[1][2] += a1 * bw.z; accW[1][3] += a1 * bw.w;
            accW[2][0] += a2 * bw.x; accW[2][1] += a2 * bw.y;
            accW[2][2] += a2 * bw.z; accW[2][3] += a2 * bw.w;
            accW[3][0] += a3 * bw.x; accW[3][1] += a3 * bw.y;
            accW[3][2] += a3 * bw.z; accW[3][3] += a3 * bw.w;

            accS[0][0] += a0 * bs.x; accS[0][1] += a0 * bs.y;
            accS[0][2] += a0 * bs.z; accS[0][3] += a0 * bs.w;
            accS[1][0] += a1 * bs.x; accS[1][1] += a1 * bs.y;
            accS[1][2] += a1 * bs.z; accS[1][3] += a1 * bs.w;
            accS[2][0] += a2 * bs.x; accS[2][1] += a2 * bs.y;
            accS[2][2] += a2 * bs.z; accS[2][3] += a2 * bs.w;
            accS[3][0] += a3 * bs.x; accS[3][1] += a3 * bs.y;
            accS[3][2] += a3 * bs.z; accS[3][3] += a3 * bs.w;
        }
        __syncthreads();
    }

    #pragma unroll
    for (int i = 0; i < 4; i++) {
        int gr = row0 + ty4 + i;
        if (gr < N_NODES) {
            long off = (long)gr * HF + colbase + tx4;
            *(float4*)(proj + off) =
                make_float4(accW[i][0], accW[i][1], accW[i][2], accW[i][3]);
            *(float4*)(acc + off) =
                make_float4(accS[i][0], accS[i][1], accS[i][2], accS[i][3]);
        }
    }
}

// ============================================================================
// K2: per-node attention scores (one warp per node), also zeroes denom.
// ============================================================================
__global__ __launch_bounds__(256) void node_scores(
    const float* __restrict__ proj,
    const float* __restrict__ a_src, const float* __restrict__ a_trg,
    float* __restrict__ ssrc, float* __restrict__ strg,
    float* __restrict__ denom)
{
    int warp = (blockIdx.x * blockDim.x + threadIdx.x) >> 5;
    int lane = threadIdx.x & 31;
    if (warp >= N_NODES) return;

    const float4* pr  = (const float4*)(proj + (long)warp * HF);
    const float4* as4 = (const float4*)a_src;   // [H,F] flat == 256 floats
    const float4* at4 = (const float4*)a_trg;

    float ps = 0.f, pt = 0.f;
    #pragma unroll
    for (int i = 0; i < 2; i++) {
        float4 p = pr[lane * 2 + i];
        float4 a = as4[lane * 2 + i];
        float4 b = at4[lane * 2 + i];
        ps += p.x * a.x + p.y * a.y + p.z * a.z + p.w * a.w;
        pt += p.x * b.x + p.y * b.y + p.z * b.z + p.w * b.w;
    }
    // reduce within 8-lane groups (one head per group of 64 features)
    #pragma unroll
    for (int o = 4; o >= 1; o >>= 1) {
        ps += __shfl_xor_sync(0xffffffffu, ps, o);
        pt += __shfl_xor_sync(0xffffffffu, pt, o);
    }
    if ((lane & 7) == 0) {
        int h = lane >> 3;
        ssrc[warp * NHEADS + h]  = ps;
        strg[warp * NHEADS + h]  = pt;
        denom[warp * NHEADS + h] = 0.f;
    }
}

// ============================================================================
// K3: per-edge exp(leaky(score)) + denom accumulation. One thread per edge.
// ============================================================================
__global__ __launch_bounds__(256) void edge_scores(
    const int* __restrict__ esrc, const int* __restrict__ etrg,
    const float* __restrict__ ssrc, const float* __restrict__ strg,
    float* __restrict__ ex, float* __restrict__ denom, int n_edges)
{
    int e = blockIdx.x * blockDim.x + threadIdx.x;
    if (e >= n_edges) return;
    int s = esrc[e], t = etrg[e];
    float4 a = *(const float4*)(ssrc + (long)s * NHEADS);
    float4 b = *(const float4*)(strg + (long)t * NHEADS);
    float4 v;
    v.x = __expf(lrelu(a.x + b.x));
    v.y = __expf(lrelu(a.y + b.y));
    v.z = __expf(lrelu(a.z + b.z));
    v.w = __expf(lrelu(a.w + b.w));
    *(float4*)(ex + (long)e * NHEADS) = v;
    red_add_v4(denom + (long)t * NHEADS, v);
}

// ============================================================================
// K4: weighted aggregation. One warp per edge; lane covers 8 consecutive
// features (f = lane*8 .. lane*8+7), so head = lane>>3 is lane-constant.
// ============================================================================
__global__ __launch_bounds__(256) void edge_agg(
    const int* __restrict__ esrc, const int* __restrict__ etrg,
    const float* __restrict__ proj, const float* __restrict__ ex,
    const float* __restrict__ denom, float* __restrict__ out, int n_edges)
{
    int warp = (blockIdx.x * blockDim.x + threadIdx.x) >> 5;
    int lane = threadIdx.x & 31;
    if (warp >= n_edges) return;

    int s = esrc[warp], t = etrg[warp];
    int h = lane >> 3;
    float attn = ex[(long)warp * NHEADS + h] /
                 (denom[(long)t * NHEADS + h] + 1e-16f);

    const float4* ps = (const float4*)(proj + (long)s * HF);
    float4 p0 = ps[lane * 2 + 0];
    float4 p1 = ps[lane * 2 + 1];
    p0.x *= attn; p0.y *= attn; p0.z *= attn; p0.w *= attn;
    p1.x *= attn; p1.y *= attn; p1.z *= attn; p1.w *= attn;

    float* dst = out + (long)t * HF + lane * 8;
    red_add_v4(dst,     p0);
    red_add_v4(dst + 4, p1);
}

// ============================================================================
// K5: finalize: out = leaky(acc + bias)
// ============================================================================
__global__ __launch_bounds__(256) void finalize(
    float* __restrict__ out, const float* __restrict__ bias, int total)
{
    int i = blockIdx.x * blockDim.x + threadIdx.x;
    if (i >= total) return;
    float v = out[i] + bias[i & (HF - 1)];
    out[i] = lrelu(v);
}

// ============================================================================
extern "C" void kernel_launch(void* const* d_in, const int* in_sizes, int n_in,
                              void* d_out, int out_size)
{
    const float* x      = (const float*)d_in[0];
    const float* W      = (const float*)d_in[1];
    const float* a_src  = (const float*)d_in[2];
    const float* a_trg  = (const float*)d_in[3];
    const float* skip_w = (const float*)d_in[4];
    const float* bias   = (const float*)d_in[5];
    const int*   esrc   = (const int*)d_in[6];
    const int*   etrg   = (const int*)d_in[7];
    float* out = (float*)d_out;

    int n_edges = in_sizes[6];           // 800000

    float* proj  = nullptr;
    float* ssrc  = nullptr;
    float* strg  = nullptr;
    float* ex    = nullptr;
    float* denom = nullptr;
    cudaGetSymbolAddress((void**)&proj,  g_proj);
    cudaGetSymbolAddress((void**)&ssrc,  g_ssrc);
    cudaGetSymbolAddress((void**)&strg,  g_strg);
    cudaGetSymbolAddress((void**)&ex,    g_ex);
    cudaGetSymbolAddress((void**)&denom, g_denom);

    // K1: proj + skip projection (skip goes straight into d_out), shared A tile
    dim3 g1(4, (N_NODES + 63) / 64);
    gemm_dual<<<g1, 256>>>(x, W, skip_w, proj, out);

    // K2: node scores (+ denom zeroing). 8 warps/block.
    node_scores<<<(N_NODES + 7) / 8, 256>>>(proj, a_src, a_trg, ssrc, strg, denom);

    // K3: edge exp-scores + denom
    edge_scores<<<(n_edges + 255) / 256, 256>>>(esrc, etrg, ssrc, strg, ex, denom, n_edges);

    // K4: scatter aggregation (1 warp per edge)
    edge_agg<<<(n_edges + 7) / 8, 256>>>(esrc, etrg, proj, ex, denom, out, n_edges);

    // K5: bias + output LeakyReLU
    int total = N_NODES * HF;
    finalize<<<(total + 255) / 256, 256>>>(out, bias, total);
}

// round 5
// speedup vs baseline: 1.2908x; 1.2908x over previous
#include <cuda_runtime.h>
#include <cuda_bf16.h>

// GAT forward, CSR-fused pipeline + FFMA2 (f32x2) dual GEMM:
//   K0 zero_counts: count/cursor = 0
//   K1 gemm_dual:   proj = x@W, skipb = x@skip_w  (shared A tile, fma.rn.f32x2)
//   K2 node_scores: s_src/s_trg per (node, head)
//   K3 hist:        count[trg]++
//   K4 scan:        base = exclusive_scan(count)   (single block)
//   K5 fill:        csr_src[base[t] + slot] = src  (slot via cursor atomics)
//   K6 agg_fused:   warp per target: softmax denom in-register, gather
//                   proj[src] (2-edge unrolled), + skip + bias, LeakyReLU.
// Global max subtraction from the reference cancels in the softmax ratio
// (epsilon contribution ~1e-15 relative) and is omitted.

#define N_NODES 50000
#define E_EDGES 800000
#define KDIM    256
#define HF      256
#define NHEADS  4

#define NEG_SLOPE 0.2f
#define EX_CAP   128          // smem-cached scores per target (recompute beyond)

// ---- scratch (device globals; no allocations allowed) ----
__device__ __align__(16) float g_proj[N_NODES * HF];
__device__ __align__(16) float g_skip[N_NODES * HF];
__device__ __align__(16) float g_ssrc[N_NODES * NHEADS];
__device__ __align__(16) float g_strg[N_NODES * NHEADS];
__device__ int g_count[N_NODES];
__device__ int g_cursor[N_NODES];
__device__ int g_base[N_NODES];
__device__ int g_csr_src[E_EDGES];

__device__ __forceinline__ float lrelu(float v) {
    return v > 0.f ? v : NEG_SLOPE * v;
}

// packed fp32x2 FMA: d = a*b + d  (two independent rn-rounded fp32 FMAs)
__device__ __forceinline__ void ffma2(unsigned long long& d,
                                      unsigned long long a,
                                      unsigned long long b) {
    asm("fma.rn.f32x2 %0, %1, %2, %0;" : "+l"(d) : "l"(a), "l"(b));
}

__device__ __forceinline__ unsigned long long pack_dup(float v) {
    unsigned long long r;
    unsigned int u = __float_as_uint(v);
    asm("mov.b64 %0, {%1, %1};" : "=l"(r) : "r"(u));
    return r;
}

__device__ __forceinline__ float2 unpack2(unsigned long long v) {
    unsigned int lo, hi;
    asm("mov.b64 {%0, %1}, %2;" : "=r"(lo), "=r"(hi) : "l"(v));
    return make_float2(__uint_as_float(lo), __uint_as_float(hi));
}

// ============================================================================
// K1: dual GEMM with shared A tile, f32x2 packed FMA inner loop.
// grid = (4, ceil(N/64)), block = 256. Tile 64x64, BK=32, 4x4 micro-tile
// per output (stored as 4x2 packed f32x2 accumulators each).
// ============================================================================
__global__ __launch_bounds__(256) void gemm_dual(
    const float* __restrict__ x, const float* __restrict__ W,
    const float* __restrict__ skipw, float* __restrict__ proj,
    float* __restrict__ skipb)
{
    __shared__ __align__(16) float As[32][65];   // [k][m], padded
    __shared__ __align__(16) float BsW[32][64];  // [k][n]  (W)
    __shared__ __align__(16) float BsS[32][64];  // [k][n]  (skip_w)

    const int colbase = blockIdx.x * 64;
    const int row0 = blockIdx.y * 64;
    const int tid = threadIdx.x;
    const int tx = tid & 15;
    const int ty = tid >> 4;
    const int tx4 = tx * 4;
    const int ty4 = ty * 4;

    unsigned long long accW2[4][2] = {};
    unsigned long long accS2[4][2] = {};

    for (int kt = 0; kt < KDIM; kt += 32) {
        #pragma unroll
        for (int i = 0; i < 2; i++) {
            int v = tid + i * 256;
            int r = v >> 3;
            int c = (v & 7) * 4;
            int gr = row0 + r;
            float4 av = (gr < N_NODES)
                ? *(const float4*)(x + (long)gr * KDIM + kt + c)
                : make_float4(0.f, 0.f, 0.f, 0.f);
            As[c + 0][r] = av.x;
            As[c + 1][r] = av.y;
            As[c + 2][r] = av.z;
            As[c + 3][r] = av.w;
        }
        #pragma unroll
        for (int i = 0; i < 2; i++) {
            int v = tid + i * 256;
            int r = v >> 4;
            int c = (v & 15) * 4;
            long off = (long)(kt + r) * HF + colbase + c;
            *(float4*)&BsW[r][c] = *(const float4*)(W + off);
            *(float4*)&BsS[r][c] = *(const float4*)(skipw + off);
        }
        __syncthreads();

        #pragma unroll
        for (int k = 0; k < 32; ++k) {
            unsigned long long pa0 = pack_dup(As[k][ty4 + 0]);
            unsigned long long pa1 = pack_dup(As[k][ty4 + 1]);
            unsigned long long pa2 = pack_dup(As[k][ty4 + 2]);
            unsigned long long pa3 = pack_dup(As[k][ty4 + 3]);
            ulonglong2 bw = *(const ulonglong2*)&BsW[k][tx4];  // 2 packed pairs
            ulonglong2 bs = *(const ulonglong2*)&BsS[k][tx4];

            ffma2(accW2[0][0], pa0, bw.x);  ffma2(accW2[0][1], pa0, bw.y);
            ffma2(accW2[1][0], pa1, bw.x);  ffma2(accW2[1][1], pa1, bw.y);
            ffma2(accW2[2][0], pa2, bw.x);  ffma2(accW2[2][1], pa2, bw.y);
            ffma2(accW2[3][0], pa3, bw.x);  ffma2(accW2[3][1], pa3, bw.y);

            ffma2(accS2[0][0], pa0, bs.x);  ffma2(accS2[0][1], pa0, bs.y);
            ffma2(accS2[1][0], pa1, bs.x);  ffma2(accS2[1][1], pa1, bs.y);
            ffma2(accS2[2][0], pa2, bs.x);  ffma2(accS2[2][1], pa2, bs.y);
            ffma2(accS2[3][0], pa3, bs.x);  ffma2(accS2[3][1], pa3, bs.y);
        }
        __syncthreads();
    }

    #pragma unroll
    for (int i = 0; i < 4; i++) {
        int gr = row0 + ty4 + i;
        if (gr < N_NODES) {
            long off = (long)gr * HF + colbase + tx4;
            float2 w0 = unpack2(accW2[i][0]);
            float2 w1 = unpack2(accW2[i][1]);
            float2 s0 = unpack2(accS2[i][0]);
            float2 s1 = unpack2(accS2[i][1]);
            *(float4*)(proj + off)  = make_float4(w0.x, w0.y, w1.x, w1.y);
            *(float4*)(skipb + off) = make_float4(s0.x, s0.y, s1.x, s1.y);
        }
    }
}

// ============================================================================
// K0: zero count + cursor
// ============================================================================
__global__ __launch_bounds__(256) void zero_counts(
    int* __restrict__ count, int* __restrict__ cursor)
{
    int i = blockIdx.x * blockDim.x + threadIdx.x;
    if (i < N_NODES) { count[i] = 0; cursor[i] = 0; }
}

// ============================================================================
// K2: per-node attention scores (one warp per node).
// ============================================================================
__global__ __launch_bounds__(256) void node_scores(
    const float* __restrict__ proj,
    const float* __restrict__ a_src, const float* __restrict__ a_trg,
    float* __restrict__ ssrc, float* __restrict__ strg)
{
    int warp = (blockIdx.x * blockDim.x + threadIdx.x) >> 5;
    int lane = threadIdx.x & 31;
    if (warp >= N_NODES) return;

    const float4* pr  = (const float4*)(proj + (long)warp * HF);
    const float4* as4 = (const float4*)a_src;
    const float4* at4 = (const float4*)a_trg;

    float ps = 0.f, pt = 0.f;
    #pragma unroll
    for (int i = 0; i < 2; i++) {
        float4 p = pr[lane * 2 + i];
        float4 a = as4[lane * 2 + i];
        float4 b = at4[lane * 2 + i];
        ps += p.x * a.x + p.y * a.y + p.z * a.z + p.w * a.w;
        pt += p.x * b.x + p.y * b.y + p.z * b.z + p.w * b.w;
    }
    #pragma unroll
    for (int o = 4; o >= 1; o >>= 1) {
        ps += __shfl_xor_sync(0xffffffffu, ps, o);
        pt += __shfl_xor_sync(0xffffffffu, pt, o);
    }
    if ((lane & 7) == 0) {
        int h = lane >> 3;
        ssrc[warp * NHEADS + h] = ps;
        strg[warp * NHEADS + h] = pt;
    }
}

// ============================================================================
// K3: histogram of targets
// ============================================================================
__global__ __launch_bounds__(256) void hist(
    const int* __restrict__ etrg, int* __restrict__ count, int n_edges)
{
    int e = blockIdx.x * blockDim.x + threadIdx.x;
    if (e < n_edges) atomicAdd(&count[etrg[e]], 1);
}

// ============================================================================
// K4: exclusive scan of count -> base.  Single block, 1024 threads.
// ============================================================================
__global__ __launch_bounds__(1024) void scan_counts(
    const int* __restrict__ count, int* __restrict__ base)
{
    __shared__ int sums[1024];
    const int t = threadIdx.x;
    const int CHUNK = (N_NODES + 1023) / 1024;   // 49
    int start = t * CHUNK;
    int end = min(start + CHUNK, N_NODES);

    int s = 0;
    for (int i = start; i < end; i++) s += count[i];
    sums[t] = s;
    __syncthreads();

    #pragma unroll
    for (int off = 1; off < 1024; off <<= 1) {
        int u = (t >= off) ? sums[t - off] : 0;
        __syncthreads();
        sums[t] += u;
        __syncthreads();
    }

    int running = sums[t] - s;   // exclusive prefix for this thread's chunk
    for (int i = start; i < end; i++) {
        base[i] = running;
        running += count[i];
    }
}

// ============================================================================
// K5: fill CSR (store source node id per slot)
// ============================================================================
__global__ __launch_bounds__(256) void fill_csr(
    const int* __restrict__ esrc, const int* __restrict__ etrg,
    const int* __restrict__ base, int* __restrict__ cursor,
    int* __restrict__ csr_src, int n_edges)
{
    int e = blockIdx.x * blockDim.x + threadIdx.x;
    if (e >= n_edges) return;
    int t = etrg[e];
    int slot = atomicAdd(&cursor[t], 1);
    csr_src[base[t] + slot] = esrc[e];
}

// ============================================================================
// K6: fused softmax + aggregation + skip + bias + LeakyReLU.
// One warp per target node. Lane covers features [lane*8, lane*8+8);
// head = lane>>3 is lane-constant. Phase 2 unrolled by 2 edges for MLP.
// ============================================================================
__global__ __launch_bounds__(256) void agg_fused(
    const int* __restrict__ csr_src, const int* __restrict__ base,
    const int* __restrict__ count,
    const float* __restrict__ ssrc, const float* __restrict__ strg,
    const float* __restrict__ proj, const float* __restrict__ skipb,
    const float* __restrict__ bias, float* __restrict__ out)
{
    __shared__ float4 exbuf[8][EX_CAP];

    const int warp = (blockIdx.x * blockDim.x + threadIdx.x) >> 5;
    const int w    = (threadIdx.x >> 5);
    const int lane = threadIdx.x & 31;
    if (warp >= N_NODES) return;

    const int t   = warp;
    const int b0  = base[t];
    const int deg = count[t];
    const int h   = lane >> 3;

    const float4 bt = *(const float4*)(strg + (long)t * NHEADS);

    // ---- phase 1: scores + denom (edge-parallel across lanes) ----
    float4 dsum = make_float4(0.f, 0.f, 0.f, 0.f);
    for (int i = lane; i < deg; i += 32) {
        int s = csr_src[b0 + i];
        float4 a = *(const float4*)(ssrc + (long)s * NHEADS);
        float4 v;
        v.x = __expf(lrelu(a.x + bt.x));
        v.y = __expf(lrelu(a.y + bt.y));
        v.z = __expf(lrelu(a.z + bt.z));
        v.w = __expf(lrelu(a.w + bt.w));
        if (i < EX_CAP) exbuf[w][i] = v;
        dsum.x += v.x; dsum.y += v.y; dsum.z += v.z; dsum.w += v.w;
    }
    #pragma unroll
    for (int o = 16; o >= 1; o >>= 1) {
        dsum.x += __shfl_xor_sync(0xffffffffu, dsum.x, o);
        dsum.y += __shfl_xor_sync(0xffffffffu, dsum.y, o);
        dsum.z += __shfl_xor_sync(0xffffffffu, dsum.z, o);
        dsum.w += __shfl_xor_sync(0xffffffffu, dsum.w, o);
    }
    __syncwarp();

    float dh = (h == 0) ? dsum.x : (h == 1) ? dsum.y : (h == 2) ? dsum.z : dsum.w;
    float inv_d = 1.0f / (dh + 1e-16f);

    // per-edge attention weight, from the smem cache (or recompute past cap)
    auto attn_of = [&](int j, int s) -> float {
        float4 v;
        if (j < EX_CAP) {
            v = exbuf[w][j];
        } else {
            float4 a = *(const float4*)(ssrc + (long)s * NHEADS);
            v.x = __expf(lrelu(a.x + bt.x));
            v.y = __expf(lrelu(a.y + bt.y));
            v.z = __expf(lrelu(a.z + bt.z));
            v.w = __expf(lrelu(a.w + bt.w));
        }
        float exh = (h == 0) ? v.x : (h == 1) ? v.y : (h == 2) ? v.z : v.w;
        return exh * inv_d;
    };

    // ---- phase 2: weighted gather-accumulate, 2 edges in flight ----
    float4 acc0 = make_float4(0.f, 0.f, 0.f, 0.f);
    float4 acc1 = make_float4(0.f, 0.f, 0.f, 0.f);
    int j = 0;
    for (; j + 2 <= deg; j += 2) {
        int sA = csr_src[b0 + j];
        int sB = csr_src[b0 + j + 1];
        const float4* pA = (const float4*)(proj + (long)sA * HF);
        const float4* pB = (const float4*)(proj + (long)sB * HF);
        // issue all four 16B gathers before consuming any
        float4 a0 = pA[lane * 2 + 0];
        float4 a1 = pA[lane * 2 + 1];
        float4 c0 = pB[lane * 2 + 0];
        float4 c1 = pB[lane * 2 + 1];
        float wA = attn_of(j, sA);
        float wB = attn_of(j + 1, sB);
        acc0.x += a0.x * wA; acc0.y += a0.y * wA;
        acc0.z += a0.z * wA; acc0.w += a0.w * wA;
        acc1.x += a1.x * wA; acc1.y += a1.y * wA;
        acc1.z += a1.z * wA; acc1.w += a1.w * wA;
        acc0.x += c0.x * wB; acc0.y += c0.y * wB;
        acc0.z += c0.z * wB; acc0.w += c0.w * wB;
        acc1.x += c1.x * wB; acc1.y += c1.y * wB;
        acc1.z += c1.z * wB; acc1.w += c1.w * wB;
    }
    if (j < deg) {
        int s = csr_src[b0 + j];
        const float4* ps = (const float4*)(proj + (long)s * HF);
        float4 p0 = ps[lane * 2 + 0];
        float4 p1 = ps[lane * 2 + 1];
        float wA = attn_of(j, s);
        acc0.x += p0.x * wA; acc0.y += p0.y * wA;
        acc0.z += p0.z * wA; acc0.w += p0.w * wA;
        acc1.x += p1.x * wA; acc1.y += p1.y * wA;
        acc1.z += p1.z * wA; acc1.w += p1.w * wA;
    }

    // ---- epilogue: + skip + bias, LeakyReLU, store ----
    const float4* sk = (const float4*)(skipb + (long)t * HF);
    const float4* bi = (const float4*)bias;
    float4 s0 = sk[lane * 2 + 0];
    float4 s1 = sk[lane * 2 + 1];
    float4 g0 = bi[lane * 2 + 0];
    float4 g1 = bi[lane * 2 + 1];
    float4 o0, o1;
    o0.x = lrelu(acc0.x + s0.x + g0.x);
    o0.y = lrelu(acc0.y + s0.y + g0.y);
    o0.z = lrelu(acc0.z + s0.z + g0.z);
    o0.w = lrelu(acc0.w + s0.w + g0.w);
    o1.x = lrelu(acc1.x + s1.x + g1.x);
    o1.y = lrelu(acc1.y + s1.y + g1.y);
    o1.z = lrelu(acc1.z + s1.z + g1.z);
    o1.w = lrelu(acc1.w + s1.w + g1.w);

    float4* dst = (float4*)(out + (long)t * HF);
    dst[lane * 2 + 0] = o0;
    dst[lane * 2 + 1] = o1;
}

// ============================================================================
extern "C" void kernel_launch(void* const* d_in, const int* in_sizes, int n_in,
                              void* d_out, int out_size)
{
    const float* x      = (const float*)d_in[0];
    const float* W      = (const float*)d_in[1];
    const float* a_src  = (const float*)d_in[2];
    const float* a_trg  = (const float*)d_in[3];
    const float* skip_w = (const float*)d_in[4];
    const float* bias   = (const float*)d_in[5];
    const int*   esrc   = (const int*)d_in[6];
    const int*   etrg   = (const int*)d_in[7];
    float* out = (float*)d_out;

    int n_edges = in_sizes[6];           // 800000

    float *proj = nullptr, *skipb = nullptr, *ssrc = nullptr, *strg = nullptr;
    int *count = nullptr, *cursor = nullptr, *base = nullptr, *csr_src = nullptr;
    cudaGetSymbolAddress((void**)&proj,    g_proj);
    cudaGetSymbolAddress((void**)&skipb,   g_skip);
    cudaGetSymbolAddress((void**)&ssrc,    g_ssrc);
    cudaGetSymbolAddress((void**)&strg,    g_strg);
    cudaGetSymbolAddress((void**)&count,   g_count);
    cudaGetSymbolAddress((void**)&cursor,  g_cursor);
    cudaGetSymbolAddress((void**)&base,    g_base);
    cudaGetSymbolAddress((void**)&csr_src, g_csr_src);

    // CSR build
    zero_counts<<<(N_NODES + 255) / 256, 256>>>(count, cursor);
    hist<<<(n_edges + 255) / 256, 256>>>(etrg, count, n_edges);
    scan_counts<<<1, 1024>>>(count, base);
    fill_csr<<<(n_edges + 255) / 256, 256>>>(esrc, etrg, base, cursor,
                                             csr_src, n_edges);

    // Projections
    dim3 g1(4, (N_NODES + 63) / 64);
    gemm_dual<<<g1, 256>>>(x, W, skip_w, proj, skipb);

    // Node scores
    node_scores<<<(N_NODES + 7) / 8, 256>>>(proj, a_src, a_trg, ssrc, strg);

    // Fused softmax + aggregation + skip + bias + activation
    agg_fused<<<(N_NODES + 7) / 8, 256>>>(csr_src, base, count, ssrc, strg,
                                          proj, skipb, bias, out);
}